// round 5
// baseline (speedup 1.0000x reference)
#include <cuda_runtime.h>
#include <cuda_bf16.h>
#include <mma.h>

using namespace nvcuda;

#define H    256
#define AH   128
#define NHET 3
#define BSEG 64
#define TM   128
#define KC   16
#define NKC  (H / KC)      // 16
#define CLD  132           // padded fp32 C row

// scratch (sanctioned __device__ globals)
__device__ float g_S[BSEG * H];
__device__ float g_denom[BSEG];

// ---------- batch dtype handling (int32 vs int64, auto-detected) ----------
__device__ __forceinline__ int batch_is64(const void* b, int N) {
    // int64 LE: word N-1 is the high half of a 0..63 value -> 0. int32: max seg id != 0.
    return ((const int*)b)[N - 1] == 0;
}
__device__ __forceinline__ int bval(const void* b, int i, int is64) {
    return is64 ? (int)((const long long*)b)[i] : ((const int*)b)[i];
}
__device__ int seg_lower_bound(const void* b, int N, int s, int is64) {
    int lo = 0, hi = N;
    while (lo < hi) {
        int m = (lo + hi) >> 1;
        if (bval(b, m, is64) < s) lo = m + 1; else hi = m;
    }
    return lo;
}

__global__ void zero_kernel() {
    int t = blockIdx.x * blockDim.x + threadIdx.x;
    if (t < BSEG * H) g_S[t] = 0.0f;
    if (t < BSEG) g_denom[t] = 0.0f;
}

__device__ __forceinline__ void split_bf16(float v, __nv_bfloat16& hi, __nv_bfloat16& lo) {
    hi = __float2bfloat16(v);
    lo = __float2bfloat16(v - __bfloat162float(hi));
}

// ---------------- K1: fused gate GEMM (wmma bf16 split) + exp + segment accum ----------------
// grid = ceil(N/128), block = 256 (8 warps). Dynamic smem: C[128][132] f32 + A/B bf16 tiles.
__global__ __launch_bounds__(256, 2)
void gate_kernel(const float* __restrict__ x,
                 const float* __restrict__ het,
                 const void*  __restrict__ batch,
                 const float* __restrict__ W1,
                 const float* __restrict__ b1,
                 const float* __restrict__ W2,
                 const float* __restrict__ b2,
                 float* __restrict__ e_out,
                 int N) {
    extern __shared__ char dynsmem[];
    float* C = (float*)dynsmem;                                   // 128*132 f32
    __nv_bfloat16* As_hi = (__nv_bfloat16*)(dynsmem + TM * CLD * 4);
    __nv_bfloat16* As_lo = As_hi + TM * KC;
    __nv_bfloat16* Bs_hi = As_lo + TM * KC;
    __nv_bfloat16* Bs_lo = Bs_hi + KC * AH;

    __shared__ float red[256];
    __shared__ float e_s[TM];
    __shared__ int   bat_s[TM];

    const int tid = threadIdx.x;
    const int w   = tid >> 5;              // warp 0..7 -> rows [16w, 16w+16)
    const int m0  = blockIdx.x * TM;

    wmma::fragment<wmma::accumulator, 16, 16, 16, float> acc[8];
#pragma unroll
    for (int t = 0; t < 8; ++t) wmma::fill_fragment(acc[t], 0.0f);

    for (int c = 0; c < NKC; ++c) {
        __syncthreads();
        // x chunk -> As (hi/lo): 128 rows x 16 k = 512 float4
#pragma unroll
        for (int it = 0; it < 2; ++it) {
            int id  = it * 256 + tid;
            int row = id >> 2, c4 = id & 3;
            int g   = m0 + row;
            float4 v = (g < N) ? *reinterpret_cast<const float4*>(&x[(long)g * H + c * KC + c4 * 4])
                               : make_float4(0.f, 0.f, 0.f, 0.f);
            float vv[4] = {v.x, v.y, v.z, v.w};
#pragma unroll
            for (int q = 0; q < 4; ++q) {
                __nv_bfloat16 hi, lo;
                split_bf16(vv[q], hi, lo);
                As_hi[row * KC + c4 * 4 + q] = hi;
                As_lo[row * KC + c4 * 4 + q] = lo;
            }
        }
        // W1 chunk -> Bs (hi/lo): 16 k x 128 cols = 512 float4
#pragma unroll
        for (int it = 0; it < 2; ++it) {
            int id = it * 256 + tid;
            int kr = id >> 5, c4 = id & 31;
            float4 v = *reinterpret_cast<const float4*>(&W1[(long)(c * KC + kr) * AH + c4 * 4]);
            float vv[4] = {v.x, v.y, v.z, v.w};
#pragma unroll
            for (int q = 0; q < 4; ++q) {
                __nv_bfloat16 hi, lo;
                split_bf16(vv[q], hi, lo);
                Bs_hi[kr * AH + c4 * 4 + q] = hi;
                Bs_lo[kr * AH + c4 * 4 + q] = lo;
            }
        }
        __syncthreads();

        wmma::fragment<wmma::matrix_a, 16, 16, 16, __nv_bfloat16, wmma::row_major> a_hi, a_lo;
        wmma::load_matrix_sync(a_hi, As_hi + w * 16 * KC, KC);
        wmma::load_matrix_sync(a_lo, As_lo + w * 16 * KC, KC);
#pragma unroll
        for (int t = 0; t < 8; ++t) {
            wmma::fragment<wmma::matrix_b, 16, 16, 16, __nv_bfloat16, wmma::row_major> b_hi, b_lo;
            wmma::load_matrix_sync(b_hi, Bs_hi + t * 16, AH);
            wmma::load_matrix_sync(b_lo, Bs_lo + t * 16, AH);
            wmma::mma_sync(acc[t], a_hi, b_hi, acc[t]);
            wmma::mma_sync(acc[t], a_lo, b_hi, acc[t]);
            wmma::mma_sync(acc[t], a_hi, b_lo, acc[t]);
        }
    }

    // store pre-activations (x@W1 part) to C
    __syncthreads();
#pragma unroll
    for (int t = 0; t < 8; ++t)
        wmma::store_matrix_sync(C + (w * 16) * CLD + t * 16, acc[t], CLD, wmma::mem_row_major);
    __syncthreads();

    // epilogue: het + bias + tanh + W2 dot. 256 threads = 128 rows x 2 col-halves
    {
        const int r  = tid >> 1;
        const int hf = tid & 1;
        const int g  = m0 + r;
        float s = 0.f;
        if (g < N) {
            float h0 = het[(long)g * NHET + 0];
            float h1 = het[(long)g * NHET + 1];
            float h2 = het[(long)g * NHET + 2];
            const int j0 = hf * 64;
#pragma unroll 8
            for (int j = j0; j < j0 + 64; ++j) {
                float v = C[r * CLD + j] + b1[j]
                        + h0 * W1[(long)(H + 0) * AH + j]
                        + h1 * W1[(long)(H + 1) * AH + j]
                        + h2 * W1[(long)(H + 2) * AH + j];
                s += tanhf(v) * W2[j];
            }
        }
        red[tid] = s;
    }
    __syncthreads();

    const int is64   = batch_is64(batch, N);
    const int mcount = (N - m0 < TM) ? (N - m0) : TM;
    if (tid < TM) {
        int g = m0 + tid;
        if (g < N) {
            float e = expf(red[2 * tid] + red[2 * tid + 1] + b2[0]);
            e_out[g]   = e;           // staged into attn region of d_out
            e_s[tid]   = e;
            bat_s[tid] = bval(batch, g, is64);
        } else {
            e_s[tid]   = 0.f;
            bat_s[tid] = -1;
        }
    }
    __syncthreads();

    // denom: run-length accumulate (sorted batch), one atomic per run
    if (tid == 0) {
        float a = 0.f;
        int cur = bat_s[0];
        for (int i = 0; i < mcount; ++i) {
            int bb = bat_s[i];
            if (bb != cur) {
                atomicAdd(&g_denom[cur], a);
                a = 0.f;
                cur = bb;
            }
            a += e_s[i];
        }
        if (cur >= 0) atomicAdd(&g_denom[cur], a);
    }

    // weighted column sums: thread t owns column h = t. x re-read is L2-hot (just streamed).
    {
        const int h = tid;
        float a = 0.f;
        int cur = bat_s[0];
#pragma unroll 4
        for (int i = 0; i < mcount; ++i) {
            int bb = bat_s[i];
            if (bb != cur) {
                atomicAdd(&g_S[cur * H + h], a);
                a = 0.f;
                cur = bb;
            }
            a += e_s[i] * x[(long)(m0 + i) * H + h];
        }
        if (cur >= 0) atomicAdd(&g_S[cur * H + h], a);
    }
}

// ---------------- K2: denom -> z = (S/denom)@Wv + bv ; attn = e/denom ----------------
__global__ __launch_bounds__(256)
void finalize_kernel(const void* __restrict__ batch,
                     const float* __restrict__ Wv,
                     const float* __restrict__ bv,
                     float* __restrict__ zreg,
                     float* __restrict__ attn,
                     int N) {
    __shared__ int range[2];
    __shared__ float sb[H];

    const int b   = blockIdx.x;
    const int tid = threadIdx.x;
    const int is64 = batch_is64(batch, N);
    if (tid == 0) {
        range[0] = seg_lower_bound(batch, N, b,     is64);
        range[1] = seg_lower_bound(batch, N, b + 1, is64);
    }
    __syncthreads();
    const int s0 = range[0], e0 = range[1];

    const float denom = g_denom[b];
    const float inv   = (e0 > s0) ? 1.f / denom : 0.f;

    sb[tid] = g_S[b * H + tid] * inv;
    __syncthreads();

    float acc = 0.f;
    if (e0 > s0) {
        acc = bv[tid];
#pragma unroll 8
        for (int k = 0; k < H; ++k)
            acc += sb[k] * Wv[(long)k * H + tid];
    }
    zreg[b * H + tid] = acc;

    for (int i = s0 + tid; i < e0; i += 256) attn[i] *= inv;
}

extern "C" void kernel_launch(void* const* d_in, const int* in_sizes, int n_in,
                              void* d_out, int out_size) {
    const float* x   = (const float*)d_in[0];
    const float* het = (const float*)d_in[1];
    const void*  batch = d_in[2];
    const float* W1  = (const float*)d_in[3];
    const float* b1  = (const float*)d_in[4];
    const float* W2  = (const float*)d_in[5];
    const float* b2  = (const float*)d_in[6];
    const float* Wv  = (const float*)d_in[7];
    const float* bv  = (const float*)d_in[8];
    float* out = (float*)d_out;

    const int N = in_sizes[2];
    float* zreg = out;                 // [BSEG*H]
    float* attn = out + BSEG * H;      // [N]  (e staged here)

    const int DSMEM = TM * CLD * 4 + 4 * (TM * KC) * 2 + 0 * 2 + 4 * 0
                    + 0;  // computed below precisely
    // C: 128*132*4 = 67584 ; As_hi/lo: 2*128*16*2 = 8192 ; Bs_hi/lo: 2*16*128*2 = 8192
    const int dsmem_bytes = 67584 + 8192 + 8192;   // 83968

    cudaFuncSetAttribute(gate_kernel,
                         cudaFuncAttributeMaxDynamicSharedMemorySize, dsmem_bytes);

    zero_kernel<<<65, 256>>>();
    gate_kernel<<<(N + TM - 1) / TM, 256, dsmem_bytes>>>(x, het, batch, W1, b1, W2, b2,
                                                         attn, N);
    finalize_kernel<<<BSEG, 256>>>(batch, Wv, bv, zreg, attn, N);
    (void)DSMEM; (void)n_in; (void)out_size; (void)in_sizes;
}

// round 7
// speedup vs baseline: 1.4211x; 1.4211x over previous
#include <cuda_runtime.h>
#include <cuda_bf16.h>
#include <cstdint>

#define H     256
#define AH    128
#define NHET  3
#define BSEG  64
#define TM    128
#define NPH   12                 // phases over K' = 768, 64 bf16 each
#define ASTR  144                // padded row: 72 bf16 (conflict-free ldmatrix)
#define CH    (128 * ASTR)       // 18432 B per chunk (128 rows)
#define CLD   132                // padded fp32 C row

// ---------------- device scratch (sanctioned) ----------------
__device__ float g_S[BSEG * H];
__device__ float g_denom[BSEG];
__device__ __align__(16) __nv_bfloat16 g_Wp[AH * 768];   // B' [n][k'] row-major

// ---------------- PTX helpers (sm_80+ only) ----------------
__device__ __forceinline__ uint32_t smem_u32(const void* p) {
    uint32_t a;
    asm("{ .reg .u64 t; cvta.to.shared.u64 t, %1; cvt.u32.u64 %0, t; }" : "=r"(a) : "l"(p));
    return a;
}
__device__ __forceinline__ void ldsm4(uint32_t* r, uint32_t a) {
    asm volatile("ldmatrix.sync.aligned.m8n8.x4.shared.b16 {%0,%1,%2,%3}, [%4];"
                 : "=r"(r[0]), "=r"(r[1]), "=r"(r[2]), "=r"(r[3]) : "r"(a));
}
__device__ __forceinline__ void mma16816(float* c, const uint32_t* a, const uint32_t* b) {
    asm volatile("mma.sync.aligned.m16n8k16.row.col.f32.bf16.bf16.f32 "
                 "{%0,%1,%2,%3}, {%4,%5,%6,%7}, {%8,%9}, {%0,%1,%2,%3};"
                 : "+f"(c[0]), "+f"(c[1]), "+f"(c[2]), "+f"(c[3])
                 : "r"(a[0]), "r"(a[1]), "r"(a[2]), "r"(a[3]), "r"(b[0]), "r"(b[1]));
}

// ---------- batch dtype handling (int32 vs int64, auto-detected) ----------
__device__ __forceinline__ int batch_is64(const void* b, int N) {
    return ((const int*)b)[N - 1] == 0;
}
__device__ __forceinline__ int bval(const void* b, int i, int is64) {
    return is64 ? (int)((const long long*)b)[i] : ((const int*)b)[i];
}
__device__ int seg_lower_bound(const void* b, int N, int s, int is64) {
    int lo = 0, hi = N;
    while (lo < hi) { int m = (lo + hi) >> 1; if (bval(b, m, is64) < s) lo = m + 1; else hi = m; }
    return lo;
}

__global__ void zero_kernel() {
    int t = blockIdx.x * blockDim.x + threadIdx.x;
    if (t < BSEG * H) g_S[t] = 0.0f;
    if (t < BSEG) g_denom[t] = 0.0f;
}

// ---------------- prep: W' = [W_hi ; W_hi ; W_lo], stored [n][k'] ----------------
__global__ void prep_kernel(const float* __restrict__ W1) {
    int id = blockIdx.x * 256 + threadIdx.x;
    if (id >= AH * 768) return;
    int n = id / 768, k = id % 768;
    __nv_bfloat16 v;
    if (k < 512) {
        v = __float2bfloat16(W1[(long)(k & 255) * AH + n]);
    } else {
        float f = W1[(long)(k - 512) * AH + n];
        __nv_bfloat16 hi = __float2bfloat16(f);
        v = __float2bfloat16(f - __bfloat162float(hi));
    }
    g_Wp[n * 768 + k] = v;
}

// ---------------- K1: HMMA gate GEMM + tanh/W2/exp epilogue + segment accum ----------------
// block = 256 (8 warps in 4x2): warp (wr, wc) -> rows [32*wr, +32), cols [64*wc, +64)
__global__ __launch_bounds__(256)
void gate_kernel(const float* __restrict__ x,
                 const float* __restrict__ het,
                 const void*  __restrict__ batch,
                 const float* __restrict__ W1,
                 const float* __restrict__ b1,
                 const float* __restrict__ W2,
                 const float* __restrict__ b2,
                 float* __restrict__ e_out,
                 int N) {
    extern __shared__ char dyn[];
    char* const ap = dyn;                 // A: 8 chunks (hi 0..3, lo 4..7)
    char* const bp = dyn + 8 * CH;        // B: 2-chunk double buffer

    __shared__ float sb_b1[AH], sb_W2[AH], sb_h0[AH], sb_h1[AH], sb_h2[AH];
    __shared__ float red[256];
    __shared__ float e_s[TM];
    __shared__ int   bat_s[TM];

    const int tid  = threadIdx.x;
    const int lane = tid & 31;
    const int w    = tid >> 5;
    const int wr   = w >> 1;              // 0..3
    const int wc   = w & 1;               // 0..1
    const int m0   = blockIdx.x * TM;

    if (tid < AH) {
        sb_b1[tid] = b1[tid];
        sb_W2[tid] = W2[tid];
        sb_h0[tid] = W1[(long)(H + 0) * AH + tid];
        sb_h1[tid] = W1[(long)(H + 1) * AH + tid];
        sb_h2[tid] = W1[(long)(H + 2) * AH + tid];
    }

    // ---- stage A: split x tile into bf16 hi/lo chunks ----
#pragma unroll 4
    for (int it = 0; it < 32; ++it) {
        int id  = it * 256 + tid;            // 0..8191 float4s
        int row = id >> 6, c4 = id & 63;
        int g   = m0 + row;
        float4 v = (g < N) ? *reinterpret_cast<const float4*>(&x[(long)g * H + c4 * 4])
                           : make_float4(0.f, 0.f, 0.f, 0.f);
        float f[4] = {v.x, v.y, v.z, v.w};
        unsigned short hb[4], lb[4];
#pragma unroll
        for (int q = 0; q < 4; ++q) {
            __nv_bfloat16 hi = __float2bfloat16(f[q]);
            __nv_bfloat16 lo = __float2bfloat16(f[q] - __bfloat162float(hi));
            hb[q] = __bfloat16_as_ushort(hi);
            lb[q] = __bfloat16_as_ushort(lo);
        }
        uint2 hpk, lpk;
        hpk.x = (uint32_t)hb[0] | ((uint32_t)hb[1] << 16);
        hpk.y = (uint32_t)hb[2] | ((uint32_t)hb[3] << 16);
        lpk.x = (uint32_t)lb[0] | ((uint32_t)lb[1] << 16);
        lpk.y = (uint32_t)lb[2] | ((uint32_t)lb[3] << 16);
        int chunk = c4 >> 4;                 // k-chunk 0..3
        int kin   = (c4 & 15) * 4;           // bf16 index within chunk row
        *reinterpret_cast<uint2*>(ap + chunk * CH + row * ASTR + kin * 2)       = hpk;
        *reinterpret_cast<uint2*>(ap + (4 + chunk) * CH + row * ASTR + kin * 2) = lpk;
    }

    // ---- preload B chunk 0 ----
    const float4* wp4 = reinterpret_cast<const float4*>(g_Wp);
    float4 breg[4];
#pragma unroll
    for (int it = 0; it < 4; ++it) {
        int id = it * 256 + tid;             // 0..1023
        int n = id >> 3, seg = id & 7;
        breg[it] = wp4[n * 96 + 0 * 8 + seg];
    }
    __syncthreads();                         // A staging visible
#pragma unroll
    for (int it = 0; it < 4; ++it) {
        int id = it * 256 + tid;
        int n = id >> 3, seg = id & 7;
        *reinterpret_cast<float4*>(bp + 0 * CH + n * ASTR + seg * 16) = breg[it];
    }
    __syncthreads();

    float acc[2][8][4];
#pragma unroll
    for (int t = 0; t < 2; ++t)
#pragma unroll
        for (int v = 0; v < 8; ++v)
#pragma unroll
            for (int q = 0; q < 4; ++q) acc[t][v][q] = 0.f;

    // precomputed ldmatrix lane addressing pieces
    const int a_row = wr * 32 + (lane & 15);
    const int a_k8  = (lane >> 4) & 1;             // +8 k for lanes 16..31
    const int b_row = wc * 64 + (lane & 7) + ((lane >> 4) & 1) * 8;
    const int b_k8  = (lane >> 3) & 1;

    for (int p = 0; p < NPH; ++p) {
        if (p + 1 < NPH) {
#pragma unroll
            for (int it = 0; it < 4; ++it) {
                int id = it * 256 + tid;
                int n = id >> 3, seg = id & 7;
                breg[it] = wp4[n * 96 + (p + 1) * 8 + seg];
            }
        }
        // compute chunk p
        {
            char* const ab = ap + ((p < 8) ? p : (p - 8)) * CH;
            char* const bb = bp + (p & 1) * CH;
#pragma unroll
            for (int ks = 0; ks < 4; ++ks) {
                uint32_t afrag[2][4], bfrag[4][4];
#pragma unroll
                for (int t = 0; t < 2; ++t)
                    ldsm4(afrag[t], smem_u32(ab + (a_row + t * 16) * ASTR
                                             + (ks * 16 + a_k8 * 8) * 2));
#pragma unroll
                for (int u = 0; u < 4; ++u)
                    ldsm4(bfrag[u], smem_u32(bb + (b_row + u * 16) * ASTR
                                             + (ks * 16 + b_k8 * 8) * 2));
#pragma unroll
                for (int t = 0; t < 2; ++t)
#pragma unroll
                    for (int v = 0; v < 8; ++v)
                        mma16816(acc[t][v], afrag[t], bfrag[v >> 1] + (v & 1) * 2);
            }
        }
        __syncthreads();
        if (p + 1 < NPH) {
#pragma unroll
            for (int it = 0; it < 4; ++it) {
                int id = it * 256 + tid;
                int n = id >> 3, seg = id & 7;
                *reinterpret_cast<float4*>(bp + ((p + 1) & 1) * CH + n * ASTR + seg * 16) = breg[it];
            }
            __syncthreads();
        }
    }

    // ---- store C into A region (all MMA reads done: bar above) ----
    float* const C = reinterpret_cast<float*>(ap);
#pragma unroll
    for (int t = 0; t < 2; ++t)
#pragma unroll
        for (int v = 0; v < 8; ++v) {
            int rg = wr * 32 + t * 16 + (lane >> 2);
            int cg = wc * 64 + v * 8 + (lane & 3) * 2;
            *reinterpret_cast<float2*>(&C[rg * CLD + cg])       = make_float2(acc[t][v][0], acc[t][v][1]);
            *reinterpret_cast<float2*>(&C[(rg + 8) * CLD + cg]) = make_float2(acc[t][v][2], acc[t][v][3]);
        }
    __syncthreads();

    // ---- epilogue: het + bias + tanh + W2 dot (2 threads per row) ----
    {
        const int r  = tid >> 1;
        const int hf = tid & 1;
        const int g  = m0 + r;
        float s = 0.f;
        if (g < N) {
            float h0 = het[(long)g * NHET + 0];
            float h1 = het[(long)g * NHET + 1];
            float h2 = het[(long)g * NHET + 2];
            const int j0 = hf * 64;
#pragma unroll 8
            for (int j = j0; j < j0 + 64; ++j) {
                float v = C[r * CLD + j] + sb_b1[j]
                        + h0 * sb_h0[j] + h1 * sb_h1[j] + h2 * sb_h2[j];
                s += tanhf(v) * sb_W2[j];
            }
        }
        red[tid] = s;
    }
    __syncthreads();

    const int is64   = batch_is64(batch, N);
    const int mcount = (N - m0 < TM) ? (N - m0) : TM;
    if (tid < TM) {
        int g = m0 + tid;
        if (g < N) {
            float e = expf(red[2 * tid] + red[2 * tid + 1] + b2[0]);
            e_out[g]   = e;
            e_s[tid]   = e;
            bat_s[tid] = bval(batch, g, is64);
        } else {
            e_s[tid]   = 0.f;
            bat_s[tid] = -1;
        }
    }
    __syncthreads();

    // ---- denom: run-length accumulate (sorted batch) ----
    if (tid == 0) {
        float a = 0.f;
        int cur = bat_s[0];
        for (int i = 0; i < mcount; ++i) {
            int bb = bat_s[i];
            if (bb != cur) { atomicAdd(&g_denom[cur], a); a = 0.f; cur = bb; }
            a += e_s[i];
        }
        if (cur >= 0) atomicAdd(&g_denom[cur], a);
    }

    // ---- weighted column sums: thread t owns column h = t (x re-read is L2-hot) ----
    {
        const int h = tid;
        float a = 0.f;
        int cur = bat_s[0];
#pragma unroll 4
        for (int i = 0; i < mcount; ++i) {
            int bb = bat_s[i];
            if (bb != cur) { atomicAdd(&g_S[cur * H + h], a); a = 0.f; cur = bb; }
            a += e_s[i] * x[(long)(m0 + i) * H + h];
        }
        if (cur >= 0) atomicAdd(&g_S[cur * H + h], a);
    }
}

// ---------------- K2: denom -> z = (S/denom)@Wv + bv ; attn = e/denom ----------------
__global__ __launch_bounds__(256)
void finalize_kernel(const void* __restrict__ batch,
                     const float* __restrict__ Wv,
                     const float* __restrict__ bv,
                     float* __restrict__ zreg,
                     float* __restrict__ attn,
                     int N) {
    __shared__ int range[2];
    __shared__ float sb[H];

    const int b   = blockIdx.x;
    const int tid = threadIdx.x;
    const int is64 = batch_is64(batch, N);
    if (tid == 0) {
        range[0] = seg_lower_bound(batch, N, b,     is64);
        range[1] = seg_lower_bound(batch, N, b + 1, is64);
    }
    __syncthreads();
    const int s0 = range[0], e0 = range[1];

    const float denom = g_denom[b];
    const float inv   = (e0 > s0) ? 1.f / denom : 0.f;

    sb[tid] = g_S[b * H + tid] * inv;
    __syncthreads();

    float acc = 0.f;
    if (e0 > s0) {
        acc = bv[tid];
#pragma unroll 8
        for (int k = 0; k < H; ++k)
            acc += sb[k] * Wv[(long)k * H + tid];
    }
    zreg[b * H + tid] = acc;

    for (int i = s0 + tid; i < e0; i += 256) attn[i] *= inv;
}

extern "C" void kernel_launch(void* const* d_in, const int* in_sizes, int n_in,
                              void* d_out, int out_size) {
    const float* x   = (const float*)d_in[0];
    const float* het = (const float*)d_in[1];
    const void*  batch = d_in[2];
    const float* W1  = (const float*)d_in[3];
    const float* b1  = (const float*)d_in[4];
    const float* W2  = (const float*)d_in[5];
    const float* b2  = (const float*)d_in[6];
    const float* Wv  = (const float*)d_in[7];
    const float* bv  = (const float*)d_in[8];
    float* out = (float*)d_out;

    const int N = in_sizes[2];
    float* zreg = out;                 // [BSEG*H]
    float* attn = out + BSEG * H;      // [N] (e staged here)

    const int dsmem = 10 * CH;         // A 8 chunks + B 2 chunks = 184320 B
    cudaFuncSetAttribute(gate_kernel,
                         cudaFuncAttributeMaxDynamicSharedMemorySize, dsmem);

    zero_kernel<<<65, 256>>>();
    prep_kernel<<<(AH * 768 + 255) / 256, 256>>>(W1);
    gate_kernel<<<(N + TM - 1) / TM, 256, dsmem>>>(x, het, batch, W1, b1, W2, b2,
                                                   attn, N);
    finalize_kernel<<<BSEG, 256>>>(batch, Wv, bv, zreg, attn, N);
    (void)n_in; (void)out_size;
}

// round 12
// speedup vs baseline: 2.0724x; 1.4583x over previous
#include <cuda_runtime.h>
#include <cuda_bf16.h>
#include <cstdint>

#define H     256
#define AH    128
#define NHET  3
#define BSEG  64
#define TM    128
#define NPH   12                 // phases over K' = 768, 64 bf16 each
#define ASTR  144                // padded row: 72 bf16 (conflict-free ldmatrix)
#define CHA   (128 * ASTR + 32)  // A chunk stride (bank-shifted by 8 per chunk)
#define CHB   (128 * ASTR)       // B chunk stride

// ---------------- device scratch (sanctioned) ----------------
__device__ float g_S[BSEG * H];
__device__ float g_denom[BSEG];
__device__ __align__(16) __nv_bfloat16 g_Wp[AH * 768];   // B' [n][k'] row-major

// ---------------- PTX helpers (sm_80+ only) ----------------
__device__ __forceinline__ uint32_t smem_u32(const void* p) {
    uint32_t a;
    asm("{ .reg .u64 t; cvta.to.shared.u64 t, %1; cvt.u32.u64 %0, t; }" : "=r"(a) : "l"(p));
    return a;
}
__device__ __forceinline__ void ldsm4(uint32_t* r, uint32_t a) {
    asm volatile("ldmatrix.sync.aligned.m8n8.x4.shared.b16 {%0,%1,%2,%3}, [%4];"
                 : "=r"(r[0]), "=r"(r[1]), "=r"(r[2]), "=r"(r[3]) : "r"(a));
}
__device__ __forceinline__ void mma16816(float* c, const uint32_t* a, const uint32_t* b) {
    asm volatile("mma.sync.aligned.m16n8k16.row.col.f32.bf16.bf16.f32 "
                 "{%0,%1,%2,%3}, {%4,%5,%6,%7}, {%8,%9}, {%0,%1,%2,%3};"
                 : "+f"(c[0]), "+f"(c[1]), "+f"(c[2]), "+f"(c[3])
                 : "r"(a[0]), "r"(a[1]), "r"(a[2]), "r"(a[3]), "r"(b[0]), "r"(b[1]));
}

// ---------- batch dtype handling (int32 vs int64, auto-detected) ----------
__device__ __forceinline__ int batch_is64(const void* b, int N) {
    return ((const int*)b)[N - 1] == 0;
}
__device__ __forceinline__ int bval(const void* b, int i, int is64) {
    return is64 ? (int)((const long long*)b)[i] : ((const int*)b)[i];
}
__device__ int seg_lower_bound(const void* b, int N, int s, int is64) {
    int lo = 0, hi = N;
    while (lo < hi) { int m = (lo + hi) >> 1; if (bval(b, m, is64) < s) lo = m + 1; else hi = m; }
    return lo;
}

__global__ void zero_kernel() {
    int t = blockIdx.x * blockDim.x + threadIdx.x;
    if (t < BSEG * H) g_S[t] = 0.0f;
    if (t < BSEG) g_denom[t] = 0.0f;
}

// ---------------- prep: W' = [W_hi ; W_hi ; W_lo], stored [n][k'] ----------------
__global__ void prep_kernel(const float* __restrict__ W1) {
    int id = blockIdx.x * 256 + threadIdx.x;
    if (id >= AH * 768) return;
    int n = id / 768, k = id % 768;
    __nv_bfloat16 v;
    if (k < 512) {
        v = __float2bfloat16(W1[(long)(k & 255) * AH + n]);
    } else {
        float f = W1[(long)(k - 512) * AH + n];
        __nv_bfloat16 hi = __float2bfloat16(f);
        v = __float2bfloat16(f - __bfloat162float(hi));
    }
    g_Wp[n * 768 + k] = v;
}

// ---------------- K1: HMMA gate GEMM + register epilogue + smem segment accum ----------------
__global__ __launch_bounds__(256)
void gate_kernel(const float* __restrict__ x,
                 const float* __restrict__ het,
                 const void*  __restrict__ batch,
                 const float* __restrict__ W1,
                 const float* __restrict__ b1,
                 const float* __restrict__ W2,
                 const float* __restrict__ b2,
                 float* __restrict__ e_out,
                 int N) {
    extern __shared__ char dyn[];
    char* const ap = dyn;                 // A: 8 chunks (hi 0..3, lo 4..7), stride CHA
    char* const bp = dyn + 8 * CHA;       // B: 2-chunk double buffer, stride CHB

    __shared__ float sb_b1[AH], sb_W2[AH], sb_h0[AH], sb_h1[AH], sb_h2[AH];
    __shared__ float sh_het[TM][4];
    __shared__ float red2[TM * 2];
    __shared__ float e_s[TM];
    __shared__ int   bat_s[TM];

    const int tid  = threadIdx.x;
    const int lane = tid & 31;
    const int w    = tid >> 5;
    const int wr   = w >> 1;              // 0..3
    const int wc   = w & 1;               // 0..1
    const int m0   = blockIdx.x * TM;

    if (tid < AH) {
        sb_b1[tid] = b1[tid];
        sb_W2[tid] = W2[tid];
        sb_h0[tid] = W1[(long)(H + 0) * AH + tid];
        sb_h1[tid] = W1[(long)(H + 1) * AH + tid];
        sb_h2[tid] = W1[(long)(H + 2) * AH + tid];
    }
    if (tid < TM) {
        int g = m0 + tid;
#pragma unroll
        for (int k = 0; k < NHET; ++k)
            sh_het[tid][k] = (g < N) ? het[(long)g * NHET + k] : 0.f;
    }

    // ---- stage A: split x tile into bf16 hi/lo chunks ----
#pragma unroll 4
    for (int it = 0; it < 32; ++it) {
        int id  = it * 256 + tid;            // 0..8191 float4s
        int row = id >> 6, c4 = id & 63;
        int g   = m0 + row;
        float4 v = (g < N) ? *reinterpret_cast<const float4*>(&x[(long)g * H + c4 * 4])
                           : make_float4(0.f, 0.f, 0.f, 0.f);
        float f[4] = {v.x, v.y, v.z, v.w};
        unsigned short hb[4], lb[4];
#pragma unroll
        for (int q = 0; q < 4; ++q) {
            __nv_bfloat16 hi = __float2bfloat16(f[q]);
            __nv_bfloat16 lo = __float2bfloat16(f[q] - __bfloat162float(hi));
            hb[q] = __bfloat16_as_ushort(hi);
            lb[q] = __bfloat16_as_ushort(lo);
        }
        uint2 hpk, lpk;
        hpk.x = (uint32_t)hb[0] | ((uint32_t)hb[1] << 16);
        hpk.y = (uint32_t)hb[2] | ((uint32_t)hb[3] << 16);
        lpk.x = (uint32_t)lb[0] | ((uint32_t)lb[1] << 16);
        lpk.y = (uint32_t)lb[2] | ((uint32_t)lb[3] << 16);
        int chunk = c4 >> 4;
        int kin   = (c4 & 15) * 4;
        *reinterpret_cast<uint2*>(ap + chunk * CHA + row * ASTR + kin * 2)       = hpk;
        *reinterpret_cast<uint2*>(ap + (4 + chunk) * CHA + row * ASTR + kin * 2) = lpk;
    }

    // ---- preload B chunk 0 ----
    const float4* wp4 = reinterpret_cast<const float4*>(g_Wp);
    float4 breg[4];
#pragma unroll
    for (int it = 0; it < 4; ++it) {
        int id = it * 256 + tid;
        int n = id >> 3, seg = id & 7;
        breg[it] = wp4[n * 96 + 0 * 8 + seg];
    }
    __syncthreads();
#pragma unroll
    for (int it = 0; it < 4; ++it) {
        int id = it * 256 + tid;
        int n = id >> 3, seg = id & 7;
        *reinterpret_cast<float4*>(bp + 0 * CHB + n * ASTR + seg * 16) = breg[it];
    }
    __syncthreads();

    float acc[2][8][4];
#pragma unroll
    for (int t = 0; t < 2; ++t)
#pragma unroll
        for (int v = 0; v < 8; ++v)
#pragma unroll
            for (int q = 0; q < 4; ++q) acc[t][v][q] = 0.f;

    const int a_row = wr * 32 + (lane & 15);
    const int a_k8  = (lane >> 4) & 1;
    const int b_row = wc * 64 + (lane & 7) + ((lane >> 4) & 1) * 8;
    const int b_k8  = (lane >> 3) & 1;

    for (int p = 0; p < NPH; ++p) {
        if (p + 1 < NPH) {
#pragma unroll
            for (int it = 0; it < 4; ++it) {
                int id = it * 256 + tid;
                int n = id >> 3, seg = id & 7;
                breg[it] = wp4[n * 96 + (p + 1) * 8 + seg];
            }
        }
        {
            char* const ab = ap + ((p < 8) ? p : (p - 8)) * CHA;
            char* const bb = bp + (p & 1) * CHB;
#pragma unroll
            for (int ks = 0; ks < 4; ++ks) {
                uint32_t afrag[2][4], bfrag[4][4];
#pragma unroll
                for (int t = 0; t < 2; ++t)
                    ldsm4(afrag[t], smem_u32(ab + (a_row + t * 16) * ASTR
                                             + (ks * 16 + a_k8 * 8) * 2));
#pragma unroll
                for (int u = 0; u < 4; ++u)
                    ldsm4(bfrag[u], smem_u32(bb + (b_row + u * 16) * ASTR
                                             + (ks * 16 + b_k8 * 8) * 2));
#pragma unroll
                for (int t = 0; t < 2; ++t)
#pragma unroll
                    for (int v = 0; v < 8; ++v)
                        mma16816(acc[t][v], afrag[t], bfrag[v >> 1] + (v & 1) * 2);
            }
        }
        __syncthreads();
        if (p + 1 < NPH) {
#pragma unroll
            for (int it = 0; it < 4; ++it) {
                int id = it * 256 + tid;
                int n = id >> 3, seg = id & 7;
                *reinterpret_cast<float4*>(bp + ((p + 1) & 1) * CHB + n * ASTR + seg * 16) = breg[it];
            }
            __syncthreads();
        }
    }

    // ---- register epilogue: tanh/W2 dot directly on fragments ----
    {
        const int q = lane >> 2;
        float hv[2][2][3];                 // [t][delta][k]
#pragma unroll
        for (int t = 0; t < 2; ++t)
#pragma unroll
            for (int dl = 0; dl < 2; ++dl) {
                int r = wr * 32 + t * 16 + q + dl * 8;
#pragma unroll
                for (int k = 0; k < NHET; ++k) hv[t][dl][k] = sh_het[r][k];
            }
        float rowsum[2][2] = {{0.f, 0.f}, {0.f, 0.f}};
#pragma unroll
        for (int v = 0; v < 8; ++v) {
#pragma unroll
            for (int half = 0; half < 2; ++half) {
                int j = wc * 64 + v * 8 + (lane & 3) * 2 + half;
                float cb1 = sb_b1[j], c0 = sb_h0[j], c1 = sb_h1[j], c2 = sb_h2[j];
                float cw2 = sb_W2[j];
#pragma unroll
                for (int t = 0; t < 2; ++t)
#pragma unroll
                    for (int dl = 0; dl < 2; ++dl) {
                        float pre = acc[t][v][dl * 2 + half] + cb1
                                  + hv[t][dl][0] * c0 + hv[t][dl][1] * c1 + hv[t][dl][2] * c2;
                        rowsum[t][dl] += tanhf(pre) * cw2;
                    }
            }
        }
#pragma unroll
        for (int t = 0; t < 2; ++t)
#pragma unroll
            for (int dl = 0; dl < 2; ++dl) {
                float s = rowsum[t][dl];
                s += __shfl_xor_sync(0xffffffffu, s, 1);
                s += __shfl_xor_sync(0xffffffffu, s, 2);
                if ((lane & 3) == 0) {
                    int r = wr * 32 + t * 16 + q + dl * 8;
                    red2[r * 2 + wc] = s;
                }
            }
    }
    __syncthreads();

    const int is64   = batch_is64(batch, N);
    const int mcount = (N - m0 < TM) ? (N - m0) : TM;
    if (tid < TM) {
        int g = m0 + tid;
        if (g < N) {
            float e = expf(red2[tid * 2] + red2[tid * 2 + 1] + b2[0]);
            e_out[g]   = e;
            e_s[tid]   = e;
            bat_s[tid] = bval(batch, g, is64);
        } else {
            e_s[tid]   = 0.f;
            bat_s[tid] = -1;
        }
    }
    __syncthreads();

    // ---- denom: run-length accumulate (sorted batch) ----
    if (tid == 0) {
        float a = 0.f;
        int cur = bat_s[0];
        for (int i = 0; i < mcount; ++i) {
            int bb = bat_s[i];
            if (bb != cur) { atomicAdd(&g_denom[cur], a); a = 0.f; cur = bb; }
            a += e_s[i];
        }
        if (cur >= 0) atomicAdd(&g_denom[cur], a);
    }

    // ---- weighted column sums from smem A (x ~= hi + lo), conflict-free LDS ----
    {
        const int h     = tid;
        const int chunk = h >> 6;
        const int cb    = (h & 63) * 2;
        const char* hp  = ap + chunk * CHA + cb;
        const char* lp  = ap + (4 + chunk) * CHA + cb;
        float a = 0.f;
        int cur = bat_s[0];
#pragma unroll 4
        for (int i = 0; i < mcount; ++i) {
            int bb = bat_s[i];
            if (bb != cur) { atomicAdd(&g_S[cur * H + h], a); a = 0.f; cur = bb; }
            float xv = __bfloat162float(*reinterpret_cast<const __nv_bfloat16*>(hp + i * ASTR))
                     + __bfloat162float(*reinterpret_cast<const __nv_bfloat16*>(lp + i * ASTR));
            a += e_s[i] * xv;
        }
        if (cur >= 0) atomicAdd(&g_S[cur * H + h], a);
    }
}

// ---------------- K2: z = (S/denom)@Wv + bv ----------------
__global__ __launch_bounds__(256)
void z_kernel(const void* __restrict__ batch,
              const float* __restrict__ Wv,
              const float* __restrict__ bv,
              float* __restrict__ zreg,
              int N) {
    __shared__ float sb[H];
    __shared__ int nonempty;

    const int b   = blockIdx.x;
    const int tid = threadIdx.x;
    if (tid == 0) {
        const int is64 = batch_is64(batch, N);
        int s0 = seg_lower_bound(batch, N, b, is64);
        nonempty = (s0 < N) && (bval(batch, s0, is64) == b);
    }
    __syncthreads();

    const float denom = g_denom[b];
    const float inv   = nonempty ? 1.f / denom : 0.f;
    sb[tid] = g_S[b * H + tid] * inv;
    __syncthreads();

    float acc = 0.f;
    if (nonempty) {
        acc = bv[tid];
#pragma unroll 8
        for (int k = 0; k < H; ++k)
            acc += sb[k] * Wv[(long)k * H + tid];
    }
    zreg[b * H + tid] = acc;
}

// ---------------- K3: attn = e / denom[batch] ----------------
__global__ void attn_kernel(const void* __restrict__ batch,
                            float* __restrict__ attn, int N) {
    int i = blockIdx.x * blockDim.x + threadIdx.x;
    if (i < N) {
        int b = bval(batch, i, batch_is64(batch, N));
        attn[i] = attn[i] / g_denom[b];
    }
}

extern "C" void kernel_launch(void* const* d_in, const int* in_sizes, int n_in,
                              void* d_out, int out_size) {
    const float* x   = (const float*)d_in[0];
    const float* het = (const float*)d_in[1];
    const void*  batch = d_in[2];
    const float* W1  = (const float*)d_in[3];
    const float* b1  = (const float*)d_in[4];
    const float* W2  = (const float*)d_in[5];
    const float* b2  = (const float*)d_in[6];
    const float* Wv  = (const float*)d_in[7];
    const float* bv  = (const float*)d_in[8];
    float* out = (float*)d_out;

    const int N = in_sizes[2];
    float* zreg = out;                 // [BSEG*H]
    float* attn = out + BSEG * H;      // [N] (e staged here)

    const int dsmem = 8 * CHA + 2 * CHB;   // 147712 + 36864 = 184576
    cudaFuncSetAttribute(gate_kernel,
                         cudaFuncAttributeMaxDynamicSharedMemorySize, dsmem);

    zero_kernel<<<65, 256>>>();
    prep_kernel<<<(AH * 768 + 255) / 256, 256>>>(W1);
    gate_kernel<<<(N + TM - 1) / TM, 256, dsmem>>>(x, het, batch, W1, b1, W2, b2,
                                                   attn, N);
    z_kernel<<<BSEG, 256>>>(batch, Wv, bv, zreg, N);
    attn_kernel<<<(N + 255) / 256, 256>>>(batch, attn, N);
    (void)n_in; (void)out_size;
}

// round 15
// speedup vs baseline: 2.9653x; 1.4309x over previous
#include <cuda_runtime.h>
#include <cuda_bf16.h>
#include <cstdint>

#define H     256
#define AH    128
#define NHET  3
#define BSEG  64
#define TM    64                  // rows per block (2 CTAs/SM)
#define NPH   12                  // phases over K' = 768, 64 bf16 each
#define ASTR  144                 // padded row: 72 bf16 (conflict-free ldmatrix)
#define CHA   (TM * ASTR + 32)    // A chunk stride (bank-shifted per chunk)

// ---------------- device scratch (sanctioned) ----------------
__device__ float g_S[BSEG * H];
__device__ float g_denom[BSEG];
// B in fragment order: uint2 per (phase, ks, n8-group, lane)
//   word0 = {B[k,n], B[k+1,n]}, word1 = {B[k+8,n], B[k+9,n]}
//   n = ng*8 + (lane>>2), k = p*64 + ks*16 + (lane&3)*2
__device__ __align__(16) uint2 g_Wf[NPH * 4 * 16 * 32];

// ---------------- PTX helpers (sm_80+ only) ----------------
__device__ __forceinline__ uint32_t smem_u32(const void* p) {
    uint32_t a;
    asm("{ .reg .u64 t; cvta.to.shared.u64 t, %1; cvt.u32.u64 %0, t; }" : "=r"(a) : "l"(p));
    return a;
}
__device__ __forceinline__ void ldsm4(uint32_t* r, uint32_t a) {
    asm volatile("ldmatrix.sync.aligned.m8n8.x4.shared.b16 {%0,%1,%2,%3}, [%4];"
                 : "=r"(r[0]), "=r"(r[1]), "=r"(r[2]), "=r"(r[3]) : "r"(a));
}
__device__ __forceinline__ void mma16816(float* c, const uint32_t* a, uint32_t b0, uint32_t b1) {
    asm volatile("mma.sync.aligned.m16n8k16.row.col.f32.bf16.bf16.f32 "
                 "{%0,%1,%2,%3}, {%4,%5,%6,%7}, {%8,%9}, {%0,%1,%2,%3};"
                 : "+f"(c[0]), "+f"(c[1]), "+f"(c[2]), "+f"(c[3])
                 : "r"(a[0]), "r"(a[1]), "r"(a[2]), "r"(a[3]), "r"(b0), "r"(b1));
}

// ---------- batch dtype handling (int32 vs int64, auto-detected) ----------
__device__ __forceinline__ int batch_is64(const void* b, int N) {
    return ((const int*)b)[N - 1] == 0;
}
__device__ __forceinline__ int bval(const void* b, int i, int is64) {
    return is64 ? (int)((const long long*)b)[i] : ((const int*)b)[i];
}
__device__ int seg_lower_bound(const void* b, int N, int s, int is64) {
    int lo = 0, hi = N;
    while (lo < hi) { int m = (lo + hi) >> 1; if (bval(b, m, is64) < s) lo = m + 1; else hi = m; }
    return lo;
}

__global__ void zero_kernel() {
    int t = blockIdx.x * blockDim.x + threadIdx.x;
    if (t < BSEG * H) g_S[t] = 0.0f;
    if (t < BSEG) g_denom[t] = 0.0f;
}

// ---------------- prep: W' = [W_hi ; W_hi ; W_lo] -> fragment-order g_Wf ----------------
// W'(n, k): k<512 -> bf16(W1[k&255][n]); k>=512 -> bf16(W1[k-512][n] - hi)
__device__ __forceinline__ unsigned short wprime(const float* W1, int n, int k) {
    if (k < 512) {
        return __bfloat16_as_ushort(__float2bfloat16(W1[(long)(k & 255) * AH + n]));
    } else {
        float f = W1[(long)(k - 512) * AH + n];
        __nv_bfloat16 hi = __float2bfloat16(f);
        return __bfloat16_as_ushort(__float2bfloat16(f - __bfloat162float(hi)));
    }
}
__global__ void prep_kernel(const float* __restrict__ W1) {
    int id = blockIdx.x * 256 + threadIdx.x;     // 0 .. 24575
    if (id >= NPH * 4 * 16 * 32) return;
    int lane = id & 31;
    int ng   = (id >> 5) & 15;
    int ks   = (id >> 9) & 3;
    int p    = id >> 11;
    int n = ng * 8 + (lane >> 2);
    int k = p * 64 + ks * 16 + (lane & 3) * 2;
    unsigned short v00 = wprime(W1, n, k);
    unsigned short v01 = wprime(W1, n, k + 1);
    unsigned short v10 = wprime(W1, n, k + 8);
    unsigned short v11 = wprime(W1, n, k + 9);
    uint2 o;
    o.x = (uint32_t)v00 | ((uint32_t)v01 << 16);
    o.y = (uint32_t)v10 | ((uint32_t)v11 << 16);
    g_Wf[id] = o;
}

// ---------------- K1: HMMA gate GEMM (barrier-free mainloop) ----------------
// block = 256 (8 warps as 2x4): warp (wr, wc) -> rows [32wr,+32), cols [32wc,+32)
__global__ __launch_bounds__(256, 2)
void gate_kernel(const float* __restrict__ x,
                 const float* __restrict__ het,
                 const void*  __restrict__ batch,
                 const float* __restrict__ W1,
                 const float* __restrict__ b1,
                 const float* __restrict__ W2,
                 const float* __restrict__ b2,
                 float* __restrict__ e_out,
                 int N) {
    extern __shared__ char dyn[];
    char* const ap = dyn;                 // A: 8 chunks (hi 0..3, lo 4..7), stride CHA

    __shared__ float sb_b1[AH], sb_W2[AH], sb_h0[AH], sb_h1[AH], sb_h2[AH];
    __shared__ float sh_het[TM][4];
    __shared__ float red4[TM][4];
    __shared__ float e_s[TM];
    __shared__ int   bat_s[TM];

    const int tid  = threadIdx.x;
    const int lane = tid & 31;
    const int w    = tid >> 5;
    const int wr   = w >> 2;              // 0..1
    const int wc   = w & 3;               // 0..3
    const int m0   = blockIdx.x * TM;

    if (tid < AH) {
        sb_b1[tid] = b1[tid];
        sb_W2[tid] = W2[tid];
        sb_h0[tid] = W1[(long)(H + 0) * AH + tid];
        sb_h1[tid] = W1[(long)(H + 1) * AH + tid];
        sb_h2[tid] = W1[(long)(H + 2) * AH + tid];
    }
    if (tid < TM) {
        int g = m0 + tid;
#pragma unroll
        for (int k = 0; k < NHET; ++k)
            sh_het[tid][k] = (g < N) ? het[(long)g * NHET + k] : 0.f;
    }

    // ---- stage A: split x tile into bf16 hi/lo chunks (64 rows x 64 float4) ----
#pragma unroll 4
    for (int it = 0; it < 16; ++it) {
        int id  = it * 256 + tid;            // 0..4095 float4s
        int row = id >> 6, c4 = id & 63;
        int g   = m0 + row;
        float4 v = (g < N) ? *reinterpret_cast<const float4*>(&x[(long)g * H + c4 * 4])
                           : make_float4(0.f, 0.f, 0.f, 0.f);
        float f[4] = {v.x, v.y, v.z, v.w};
        unsigned short hb[4], lb[4];
#pragma unroll
        for (int q = 0; q < 4; ++q) {
            __nv_bfloat16 hi = __float2bfloat16(f[q]);
            __nv_bfloat16 lo = __float2bfloat16(f[q] - __bfloat162float(hi));
            hb[q] = __bfloat16_as_ushort(hi);
            lb[q] = __bfloat16_as_ushort(lo);
        }
        uint2 hpk, lpk;
        hpk.x = (uint32_t)hb[0] | ((uint32_t)hb[1] << 16);
        hpk.y = (uint32_t)hb[2] | ((uint32_t)hb[3] << 16);
        lpk.x = (uint32_t)lb[0] | ((uint32_t)lb[1] << 16);
        lpk.y = (uint32_t)lb[2] | ((uint32_t)lb[3] << 16);
        int chunk = c4 >> 4;                 // k-chunk 0..3
        int kin   = (c4 & 15) * 4;
        *reinterpret_cast<uint2*>(ap + chunk * CHA + row * ASTR + kin * 2)       = hpk;
        *reinterpret_cast<uint2*>(ap + (4 + chunk) * CHA + row * ASTR + kin * 2) = lpk;
    }
    __syncthreads();   // A staged (also covers sb_*/sh_het)

    float acc[2][4][4];
#pragma unroll
    for (int t = 0; t < 2; ++t)
#pragma unroll
        for (int v = 0; v < 4; ++v)
#pragma unroll
            for (int q = 0; q < 4; ++q) acc[t][v][q] = 0.f;

    const int a_row = wr * 32 + (lane & 15);
    const int a_k8  = (lane >> 4) & 1;

    // ---- barrier-free mainloop: ldsm A + LDG.64 B frags + mma ----
    for (int p = 0; p < NPH; ++p) {
        char* const ab = ap + ((p < 8) ? p : (p - 8)) * CHA;
        const uint2* const wf = g_Wf + ((p * 4) * 16) * 32;
#pragma unroll
        for (int ks = 0; ks < 4; ++ks) {
            uint32_t afrag[2][4];
#pragma unroll
            for (int t = 0; t < 2; ++t)
                ldsm4(afrag[t], smem_u32(ab + (a_row + t * 16) * ASTR
                                         + (ks * 16 + a_k8 * 8) * 2));
            uint2 bfrag[4];
#pragma unroll
            for (int v = 0; v < 4; ++v)
                bfrag[v] = wf[((ks * 16) + wc * 4 + v) * 32 + lane];
#pragma unroll
            for (int t = 0; t < 2; ++t)
#pragma unroll
                for (int v = 0; v < 4; ++v)
                    mma16816(acc[t][v], afrag[t], bfrag[v].x, bfrag[v].y);
        }
    }

    // ---- register epilogue: tanh/W2 dot directly on fragments ----
    {
        const int q = lane >> 2;
        float hv[2][2][3];
#pragma unroll
        for (int t = 0; t < 2; ++t)
#pragma unroll
            for (int dl = 0; dl < 2; ++dl) {
                int r = wr * 32 + t * 16 + q + dl * 8;
#pragma unroll
                for (int k = 0; k < NHET; ++k) hv[t][dl][k] = sh_het[r][k];
            }
        float rowsum[2][2] = {{0.f, 0.f}, {0.f, 0.f}};
#pragma unroll
        for (int v = 0; v < 4; ++v) {
#pragma unroll
            for (int half = 0; half < 2; ++half) {
                int j = wc * 32 + v * 8 + (lane & 3) * 2 + half;
                float cb1 = sb_b1[j], c0 = sb_h0[j], c1 = sb_h1[j], c2 = sb_h2[j];
                float cw2 = sb_W2[j];
#pragma unroll
                for (int t = 0; t < 2; ++t)
#pragma unroll
                    for (int dl = 0; dl < 2; ++dl) {
                        float pre = acc[t][v][dl * 2 + half] + cb1
                                  + hv[t][dl][0] * c0 + hv[t][dl][1] * c1 + hv[t][dl][2] * c2;
                        rowsum[t][dl] += tanhf(pre) * cw2;
                    }
            }
        }
#pragma unroll
        for (int t = 0; t < 2; ++t)
#pragma unroll
            for (int dl = 0; dl < 2; ++dl) {
                float s = rowsum[t][dl];
                s += __shfl_xor_sync(0xffffffffu, s, 1);
                s += __shfl_xor_sync(0xffffffffu, s, 2);
                if ((lane & 3) == 0) {
                    int r = wr * 32 + t * 16 + q + dl * 8;
                    red4[r][wc] = s;
                }
            }
    }
    __syncthreads();

    const int is64   = batch_is64(batch, N);
    const int mcount = (N - m0 < TM) ? (N - m0) : TM;
    if (tid < TM) {
        int g = m0 + tid;
        if (g < N) {
            float e = expf(red4[tid][0] + red4[tid][1] + red4[tid][2] + red4[tid][3] + b2[0]);
            e_out[g]   = e;
            e_s[tid]   = e;
            bat_s[tid] = bval(batch, g, is64);
        } else {
            e_s[tid]   = 0.f;
            bat_s[tid] = -1;
        }
    }
    __syncthreads();

    // ---- denom: run-length accumulate (sorted batch) ----
    if (tid == 0) {
        float a = 0.f;
        int cur = bat_s[0];
        for (int i = 0; i < mcount; ++i) {
            int bb = bat_s[i];
            if (bb != cur) { atomicAdd(&g_denom[cur], a); a = 0.f; cur = bb; }
            a += e_s[i];
        }
        if (cur >= 0) atomicAdd(&g_denom[cur], a);
    }

    // ---- weighted column sums from smem A (x ~= hi + lo), conflict-free LDS ----
    {
        const int h     = tid;
        const int chunk = h >> 6;
        const int cb    = (h & 63) * 2;
        const char* hp  = ap + chunk * CHA + cb;
        const char* lp  = ap + (4 + chunk) * CHA + cb;
        float a = 0.f;
        int cur = bat_s[0];
#pragma unroll 4
        for (int i = 0; i < mcount; ++i) {
            int bb = bat_s[i];
            if (bb != cur) { atomicAdd(&g_S[cur * H + h], a); a = 0.f; cur = bb; }
            float xv = __bfloat162float(*reinterpret_cast<const __nv_bfloat16*>(hp + i * ASTR))
                     + __bfloat162float(*reinterpret_cast<const __nv_bfloat16*>(lp + i * ASTR));
            a += e_s[i] * xv;
        }
        if (cur >= 0) atomicAdd(&g_S[cur * H + h], a);
    }
}

// ---------------- K2: z = (S/denom)@Wv + bv ----------------
__global__ __launch_bounds__(256)
void z_kernel(const void* __restrict__ batch,
              const float* __restrict__ Wv,
              const float* __restrict__ bv,
              float* __restrict__ zreg,
              int N) {
    __shared__ float sb[H];
    __shared__ int nonempty;

    const int b   = blockIdx.x;
    const int tid = threadIdx.x;
    if (tid == 0) {
        const int is64 = batch_is64(batch, N);
        int s0 = seg_lower_bound(batch, N, b, is64);
        nonempty = (s0 < N) && (bval(batch, s0, is64) == b);
    }
    __syncthreads();

    const float denom = g_denom[b];
    const float inv   = nonempty ? 1.f / denom : 0.f;
    sb[tid] = g_S[b * H + tid] * inv;
    __syncthreads();

    float acc = 0.f;
    if (nonempty) {
        acc = bv[tid];
#pragma unroll 8
        for (int k = 0; k < H; ++k)
            acc += sb[k] * Wv[(long)k * H + tid];
    }
    zreg[b * H + tid] = acc;
}

// ---------------- K3: attn = e / denom[batch] ----------------
__global__ void attn_kernel(const void* __restrict__ batch,
                            float* __restrict__ attn, int N) {
    int i = blockIdx.x * blockDim.x + threadIdx.x;
    if (i < N) {
        int b = bval(batch, i, batch_is64(batch, N));
        attn[i] = attn[i] / g_denom[b];
    }
}

extern "C" void kernel_launch(void* const* d_in, const int* in_sizes, int n_in,
                              void* d_out, int out_size) {
    const float* x   = (const float*)d_in[0];
    const float* het = (const float*)d_in[1];
    const void*  batch = d_in[2];
    const float* W1  = (const float*)d_in[3];
    const float* b1  = (const float*)d_in[4];
    const float* W2  = (const float*)d_in[5];
    const float* b2  = (const float*)d_in[6];
    const float* Wv  = (const float*)d_in[7];
    const float* bv  = (const float*)d_in[8];
    float* out = (float*)d_out;

    const int N = in_sizes[2];
    float* zreg = out;                 // [BSEG*H]
    float* attn = out + BSEG * H;      // [N] (e staged here)

    const int dsmem = 8 * CHA;         // 8 * 9248 = 73984
    cudaFuncSetAttribute(gate_kernel,
                         cudaFuncAttributeMaxDynamicSharedMemorySize, dsmem);

    zero_kernel<<<65, 256>>>();
    prep_kernel<<<96, 256>>>(W1);
    gate_kernel<<<(N + TM - 1) / TM, 256, dsmem>>>(x, het, batch, W1, b1, W2, b2,
                                                   attn, N);
    z_kernel<<<BSEG, 256>>>(batch, Wv, bv, zreg, N);
    attn_kernel<<<(N + 255) / 256, 256>>>(batch, attn, N);
    (void)n_in; (void)out_size;
}

// round 17
// speedup vs baseline: 3.6624x; 1.2351x over previous
#include <cuda_runtime.h>
#include <cuda_bf16.h>
#include <cstdint>

#define H     256
#define AH    128
#define NHET  3
#define BSEG  64
#define TM    64                  // rows per block
#define NPH   12                  // phases over K' = 768, 64 bf16 each
#define CHA   8192                // A chunk: 64 rows x 128 B, XOR-swizzled

// ---------------- device scratch (sanctioned) ----------------
__device__ float g_S[BSEG * H];
__device__ float g_denom[BSEG];
__device__ float g_inv[BSEG];
// B in fragment order: uint2 per (phase, ks, n8-group, lane)
__device__ __align__(16) uint2 g_Wf[NPH * 4 * 16 * 32];

// ---------------- PTX helpers (sm_80+ only) ----------------
__device__ __forceinline__ uint32_t smem_u32(const void* p) {
    uint32_t a;
    asm("{ .reg .u64 t; cvta.to.shared.u64 t, %1; cvt.u32.u64 %0, t; }" : "=r"(a) : "l"(p));
    return a;
}
__device__ __forceinline__ void ldsm4(uint32_t* r, uint32_t a) {
    asm volatile("ldmatrix.sync.aligned.m8n8.x4.shared.b16 {%0,%1,%2,%3}, [%4];"
                 : "=r"(r[0]), "=r"(r[1]), "=r"(r[2]), "=r"(r[3]) : "r"(a));
}
__device__ __forceinline__ void mma16816(float* c, const uint32_t* a, uint32_t b0, uint32_t b1) {
    asm volatile("mma.sync.aligned.m16n8k16.row.col.f32.bf16.bf16.f32 "
                 "{%0,%1,%2,%3}, {%4,%5,%6,%7}, {%8,%9}, {%0,%1,%2,%3};"
                 : "+f"(c[0]), "+f"(c[1]), "+f"(c[2]), "+f"(c[3])
                 : "r"(a[0]), "r"(a[1]), "r"(a[2]), "r"(a[3]), "r"(b0), "r"(b1));
}
__device__ __forceinline__ float fast_tanh(float v) {
    float t = __expf(2.0f * v);            // +inf / 0 endpoints give +/-1 correctly
    return 1.0f - __fdividef(2.0f, t + 1.0f);
}

// ---------- batch dtype handling (int32 vs int64, auto-detected) ----------
__device__ __forceinline__ int batch_is64(const void* b, int N) {
    return ((const int*)b)[N - 1] == 0;
}
__device__ __forceinline__ int bval(const void* b, int i, int is64) {
    return is64 ? (int)((const long long*)b)[i] : ((const int*)b)[i];
}
__device__ int seg_lower_bound(const void* b, int N, int s, int is64) {
    int lo = 0, hi = N;
    while (lo < hi) { int m = (lo + hi) >> 1; if (bval(b, m, is64) < s) lo = m + 1; else hi = m; }
    return lo;
}

__global__ void zero_kernel() {
    int t = blockIdx.x * blockDim.x + threadIdx.x;
    if (t < BSEG * H) g_S[t] = 0.0f;
    if (t < BSEG) g_denom[t] = 0.0f;
}

// ---------------- prep: W' = [W_hi ; W_hi ; W_lo] -> fragment-order g_Wf ----------------
__device__ __forceinline__ unsigned short wprime(const float* W1, int n, int k) {
    if (k < 512) {
        return __bfloat16_as_ushort(__float2bfloat16(W1[(long)(k & 255) * AH + n]));
    } else {
        float f = W1[(long)(k - 512) * AH + n];
        __nv_bfloat16 hi = __float2bfloat16(f);
        return __bfloat16_as_ushort(__float2bfloat16(f - __bfloat162float(hi)));
    }
}
__global__ void prep_kernel(const float* __restrict__ W1) {
    int id = blockIdx.x * 256 + threadIdx.x;     // 0 .. 24575
    if (id >= NPH * 4 * 16 * 32) return;
    int lane = id & 31;
    int ng   = (id >> 5) & 15;
    int ks   = (id >> 9) & 3;
    int p    = id >> 11;
    int n = ng * 8 + (lane >> 2);
    int k = p * 64 + ks * 16 + (lane & 3) * 2;
    unsigned short v00 = wprime(W1, n, k);
    unsigned short v01 = wprime(W1, n, k + 1);
    unsigned short v10 = wprime(W1, n, k + 8);
    unsigned short v11 = wprime(W1, n, k + 9);
    uint2 o;
    o.x = (uint32_t)v00 | ((uint32_t)v01 << 16);
    o.y = (uint32_t)v10 | ((uint32_t)v11 << 16);
    g_Wf[id] = o;
}

// ---------------- K1: HMMA gate GEMM (swizzled A, occ 3, barrier-free mainloop) ----------------
// block = 256 (8 warps as 2x4): warp (wr, wc) -> rows [32wr,+32), cols [32wc,+32)
__global__ __launch_bounds__(256, 3)
void gate_kernel(const float* __restrict__ x,
                 const float* __restrict__ het,
                 const void*  __restrict__ batch,
                 const float* __restrict__ W1,
                 const float* __restrict__ b1,
                 const float* __restrict__ W2,
                 const float* __restrict__ b2,
                 float* __restrict__ e_out,
                 int N) {
    extern __shared__ char dyn[];
    char* const ap = dyn;                 // A: 8 chunks (hi 0..3, lo 4..7), 8 KB each

    __shared__ float sb_b1[AH], sb_W2[AH], sb_h0[AH], sb_h1[AH], sb_h2[AH];
    __shared__ float sh_het[TM][4];
    __shared__ float red4[TM][4];
    __shared__ float e_s[TM];
    __shared__ int   bat_s[TM];

    const int tid  = threadIdx.x;
    const int lane = tid & 31;
    const int w    = tid >> 5;
    const int wr   = w >> 2;              // 0..1
    const int wc   = w & 3;               // 0..3
    const int m0   = blockIdx.x * TM;

    if (tid < AH) {
        sb_b1[tid] = b1[tid];
        sb_W2[tid] = W2[tid];
        sb_h0[tid] = W1[(long)(H + 0) * AH + tid];
        sb_h1[tid] = W1[(long)(H + 1) * AH + tid];
        sb_h2[tid] = W1[(long)(H + 2) * AH + tid];
    }
    if (tid < TM) {
        int g = m0 + tid;
#pragma unroll
        for (int k = 0; k < NHET; ++k)
            sh_het[tid][k] = (g < N) ? het[(long)g * NHET + k] : 0.f;
    }

    // ---- stage A: split x tile into bf16 hi/lo chunks (swizzled 128B rows) ----
#pragma unroll 4
    for (int it = 0; it < 16; ++it) {
        int id  = it * 256 + tid;            // 0..4095 float4s
        int row = id >> 6, c4 = id & 63;
        int g   = m0 + row;
        float4 v = (g < N) ? *reinterpret_cast<const float4*>(&x[(long)g * H + c4 * 4])
                           : make_float4(0.f, 0.f, 0.f, 0.f);
        __nv_bfloat162 h01 = __float22bfloat162_rn(make_float2(v.x, v.y));
        __nv_bfloat162 h23 = __float22bfloat162_rn(make_float2(v.z, v.w));
        float2 e01 = __bfloat1622float2(h01);
        float2 e23 = __bfloat1622float2(h23);
        __nv_bfloat162 l01 = __float22bfloat162_rn(make_float2(v.x - e01.x, v.y - e01.y));
        __nv_bfloat162 l23 = __float22bfloat162_rn(make_float2(v.z - e23.x, v.w - e23.y));
        uint2 hpk, lpk;
        hpk.x = *reinterpret_cast<uint32_t*>(&h01);
        hpk.y = *reinterpret_cast<uint32_t*>(&h23);
        lpk.x = *reinterpret_cast<uint32_t*>(&l01);
        lpk.y = *reinterpret_cast<uint32_t*>(&l23);
        int chunk = c4 >> 4;                 // k-chunk 0..3
        int ci    = c4 & 15;                 // float4 within chunk row
        // swizzle: 16B unit = ci>>1, XOR with row&7; 8B half = (ci&1)*8
        uint32_t off = (uint32_t)(row * 128 + (((ci >> 1) ^ (row & 7)) << 4) + (ci & 1) * 8);
        *reinterpret_cast<uint2*>(ap + chunk * CHA + off)       = hpk;
        *reinterpret_cast<uint2*>(ap + (4 + chunk) * CHA + off) = lpk;
    }
    __syncthreads();   // A staged (also covers sb_*/sh_het)

    float acc[2][4][4];
#pragma unroll
    for (int t = 0; t < 2; ++t)
#pragma unroll
        for (int v = 0; v < 4; ++v)
#pragma unroll
            for (int q = 0; q < 4; ++q) acc[t][v][q] = 0.f;

    const int a_row = wr * 32 + (lane & 15);
    const int a_k8  = (lane >> 4) & 1;

    // ---- barrier-free mainloop: ldsm A (swizzled) + LDG.64 B frags + mma ----
    for (int p = 0; p < NPH; ++p) {
        char* const ab = ap + ((p < 8) ? p : (p - 8)) * CHA;
        const uint2* const wf = g_Wf + ((p * 4) * 16) * 32;
#pragma unroll
        for (int ks = 0; ks < 4; ++ks) {
            uint32_t afrag[2][4];
#pragma unroll
            for (int t = 0; t < 2; ++t) {
                int r = a_row + t * 16;
                int unit = ks * 2 + a_k8;
                ldsm4(afrag[t], smem_u32(ab + r * 128 + (((unit) ^ (r & 7)) << 4)));
            }
            uint2 bfrag[4];
#pragma unroll
            for (int v = 0; v < 4; ++v)
                bfrag[v] = wf[((ks * 16) + wc * 4 + v) * 32 + lane];
#pragma unroll
            for (int t = 0; t < 2; ++t)
#pragma unroll
                for (int v = 0; v < 4; ++v)
                    mma16816(acc[t][v], afrag[t], bfrag[v].x, bfrag[v].y);
        }
    }

    // ---- register epilogue: fast tanh/W2 dot on fragments ----
    {
        const int q = lane >> 2;
        float hv[2][2][3];
#pragma unroll
        for (int t = 0; t < 2; ++t)
#pragma unroll
            for (int dl = 0; dl < 2; ++dl) {
                int r = wr * 32 + t * 16 + q + dl * 8;
#pragma unroll
                for (int k = 0; k < NHET; ++k) hv[t][dl][k] = sh_het[r][k];
            }
        float rowsum[2][2] = {{0.f, 0.f}, {0.f, 0.f}};
#pragma unroll
        for (int v = 0; v < 4; ++v) {
#pragma unroll
            for (int half = 0; half < 2; ++half) {
                int j = wc * 32 + v * 8 + (lane & 3) * 2 + half;
                float cb1 = sb_b1[j], c0 = sb_h0[j], c1 = sb_h1[j], c2 = sb_h2[j];
                float cw2 = sb_W2[j];
#pragma unroll
                for (int t = 0; t < 2; ++t)
#pragma unroll
                    for (int dl = 0; dl < 2; ++dl) {
                        float pre = acc[t][v][dl * 2 + half] + cb1
                                  + hv[t][dl][0] * c0 + hv[t][dl][1] * c1 + hv[t][dl][2] * c2;
                        rowsum[t][dl] += fast_tanh(pre) * cw2;
                    }
            }
        }
#pragma unroll
        for (int t = 0; t < 2; ++t)
#pragma unroll
            for (int dl = 0; dl < 2; ++dl) {
                float s = rowsum[t][dl];
                s += __shfl_xor_sync(0xffffffffu, s, 1);
                s += __shfl_xor_sync(0xffffffffu, s, 2);
                if ((lane & 3) == 0) {
                    int r = wr * 32 + t * 16 + q + dl * 8;
                    red4[r][wc] = s;
                }
            }
    }
    __syncthreads();

    const int is64   = batch_is64(batch, N);
    const int mcount = (N - m0 < TM) ? (N - m0) : TM;
    if (tid < TM) {
        int g = m0 + tid;
        if (g < N) {
            float e = expf(red4[tid][0] + red4[tid][1] + red4[tid][2] + red4[tid][3] + b2[0]);
            e_out[g]   = e;
            e_s[tid]   = e;
            bat_s[tid] = bval(batch, g, is64);
        } else {
            e_s[tid]   = 0.f;
            bat_s[tid] = -1;
        }
    }
    __syncthreads();

    // ---- denom: run-length accumulate (sorted batch) ----
    if (tid == 0) {
        float a = 0.f;
        int cur = bat_s[0];
        for (int i = 0; i < mcount; ++i) {
            int bb = bat_s[i];
            if (bb != cur) { atomicAdd(&g_denom[cur], a); a = 0.f; cur = bb; }
            a += e_s[i];
        }
        if (cur >= 0) atomicAdd(&g_denom[cur], a);
    }

    // ---- weighted column sums from swizzled smem A (x ~= hi + lo) ----
    {
        const int h     = tid;
        const int chunk = h >> 6;
        const int hc    = h & 63;
        const int unit  = hc >> 3;
        const int bofs  = (hc & 7) * 2;
        const char* hp  = ap + chunk * CHA;
        const char* lp  = ap + (4 + chunk) * CHA;
        float a = 0.f;
        int cur = bat_s[0];
#pragma unroll 4
        for (int i = 0; i < mcount; ++i) {
            int bb = bat_s[i];
            if (bb != cur) { atomicAdd(&g_S[cur * H + h], a); a = 0.f; cur = bb; }
            uint32_t off = (uint32_t)(i * 128 + ((unit ^ (i & 7)) << 4) + bofs);
            float xv = __bfloat162float(*reinterpret_cast<const __nv_bfloat16*>(hp + off))
                     + __bfloat162float(*reinterpret_cast<const __nv_bfloat16*>(lp + off));
            a += e_s[i] * xv;
        }
        if (cur >= 0) atomicAdd(&g_S[cur * H + h], a);
    }
}

// ---------------- K2a: seed z rows + per-segment inverse denom ----------------
__global__ __launch_bounds__(256)
void zseed_kernel(const void* __restrict__ batch,
                  const float* __restrict__ bv,
                  float* __restrict__ zreg,
                  int N) {
    __shared__ int nonempty;
    const int b   = blockIdx.x;
    const int tid = threadIdx.x;
    if (tid == 0) {
        const int is64 = batch_is64(batch, N);
        int s0 = seg_lower_bound(batch, N, b, is64);
        nonempty = (s0 < N) && (bval(batch, s0, is64) == b);
        g_inv[b] = nonempty ? 1.f / g_denom[b] : 0.f;
    }
    __syncthreads();
    zreg[b * H + tid] = nonempty ? bv[tid] : 0.f;
}

// ---------------- K2b: z += (S/denom)[k-slice] @ Wv[k-slice]  (split-k, atomics) ----------------
__global__ __launch_bounds__(256)
void zacc_kernel(const float* __restrict__ Wv,
                 float* __restrict__ zreg) {
    __shared__ float sv[64];
    const int b   = blockIdx.x >> 2;
    const int kq  = blockIdx.x & 3;
    const int tid = threadIdx.x;
    if (tid < 64) sv[tid] = g_S[b * H + kq * 64 + tid] * g_inv[b];
    __syncthreads();
    float a = 0.f;
#pragma unroll 8
    for (int k = 0; k < 64; ++k)
        a += sv[k] * Wv[(long)(kq * 64 + k) * H + tid];
    atomicAdd(&zreg[b * H + tid], a);
}

// ---------------- K3: attn = e / denom[batch] ----------------
__global__ void attn_kernel(const void* __restrict__ batch,
                            float* __restrict__ attn, int N) {
    int i = blockIdx.x * blockDim.x + threadIdx.x;
    if (i < N) {
        int b = bval(batch, i, batch_is64(batch, N));
        attn[i] = attn[i] * g_inv[b];
    }
}

extern "C" void kernel_launch(void* const* d_in, const int* in_sizes, int n_in,
                              void* d_out, int out_size) {
    const float* x   = (const float*)d_in[0];
    const float* het = (const float*)d_in[1];
    const void*  batch = d_in[2];
    const float* W1  = (const float*)d_in[3];
    const float* b1  = (const float*)d_in[4];
    const float* W2  = (const float*)d_in[5];
    const float* b2  = (const float*)d_in[6];
    const float* Wv  = (const float*)d_in[7];
    const float* bv  = (const float*)d_in[8];
    float* out = (float*)d_out;

    const int N = in_sizes[2];
    float* zreg = out;                 // [BSEG*H]
    float* attn = out + BSEG * H;      // [N] (e staged here)

    const int dsmem = 8 * CHA;         // 65536
    cudaFuncSetAttribute(gate_kernel,
                         cudaFuncAttributeMaxDynamicSharedMemorySize, dsmem);

    zero_kernel<<<65, 256>>>();
    prep_kernel<<<96, 256>>>(W1);
    gate_kernel<<<(N + TM - 1) / TM, 256, dsmem>>>(x, het, batch, W1, b1, W2, b2,
                                                   attn, N);
    zseed_kernel<<<BSEG, 256>>>(batch, bv, zreg, N);
    zacc_kernel<<<BSEG * 4, 256>>>(Wv, zreg);
    attn_kernel<<<(N + 255) / 256, 256>>>(batch, attn, N);
    (void)n_in; (void)out_size;
}